// round 9
// baseline (speedup 1.0000x reference)
#include <cuda_runtime.h>
#include <cuda_fp16.h>
#include <cstdint>
#include <cstddef>

#define NN_MAX 100000
#define NE_MAX 1600000
#define DIN 256
#define DH 128
#define SB 512

typedef unsigned long long ull;

// ---------------------------------------------------------------- scratch
__device__ __half g_xf[NN_MAX * DH];   // isr_out[n] * (x @ W_f^T)[n]  (fp16)
__device__ __half g_xb[NN_MAX * DH];   // isr_in[n]  * (x @ W_b^T)[n]  (fp16)
__device__ __half g_xa[NN_MAX * DIN];  // x as fp16
__device__ __half g_wc[256 * DIN];     // W fp16 [n][k] (Wf rows 0-127, Wb 128-255)
__device__ int   g_cnt_c[NN_MAX];
__device__ int   g_cnt_r[NN_MAX];
__device__ float g_isr_in[NN_MAX];
__device__ float g_isr_out[NN_MAX];
__device__ int   g_off_c[NN_MAX];
__device__ int   g_off_r[NN_MAX];
__device__ int   g_cur_c[NN_MAX];
__device__ int   g_cur_r[NN_MAX];
__device__ int   g_bsum_c[SB];
__device__ int   g_bsum_r[SB];
__device__ int   g_efi[NE_MAX];        // edges sorted by col: src=row
__device__ int   g_ebi[NE_MAX];        // edges sorted by row: src=col
__device__ int   g_is64;

__device__ __forceinline__ int edge_val(const void* ei, size_t idx) {
    if (g_is64) return (int)((const long long*)ei)[idx];
    return ((const int*)ei)[idx];
}

// Load 4 consecutive edge pairs (c[j], r[j]) starting at e0 (requires (E&3)==0 && e0+4<=E)
__device__ __forceinline__ void edge_quad(const void* ei, int E, int e0,
                                          int* c, int* r) {
    if (g_is64) {
        const longlong2* pc = (const longlong2*)((const long long*)ei + e0);
        const longlong2* pr = (const longlong2*)((const long long*)ei + E + e0);
        longlong2 c01 = pc[0], c23 = pc[1];
        longlong2 r01 = pr[0], r23 = pr[1];
        c[0] = (int)c01.x; c[1] = (int)c01.y; c[2] = (int)c23.x; c[3] = (int)c23.y;
        r[0] = (int)r01.x; r[1] = (int)r01.y; r[2] = (int)r23.x; r[3] = (int)r23.y;
    } else {
        int4 cc = *(const int4*)((const int*)ei + e0);
        int4 rr = *(const int4*)((const int*)ei + E + e0);
        c[0] = cc.x; c[1] = cc.y; c[2] = cc.z; c[3] = cc.w;
        r[0] = rr.x; r[1] = rr.y; r[2] = rr.z; r[3] = rr.w;
    }
}

// ---------------------------------------------------------------- dtype detect / zero
__global__ void detect_flag_kernel(const unsigned* __restrict__ w, int nwords) {
    __shared__ unsigned s;
    if (threadIdx.x == 0) s = 0;
    __syncthreads();
    unsigned acc = 0;
    for (int i = threadIdx.x; i < 16384 && 2 * i + 1 < nwords; i += blockDim.x)
        acc |= w[2 * i + 1];
    #pragma unroll
    for (int o = 16; o > 0; o >>= 1)
        acc |= __shfl_xor_sync(0xffffffffu, acc, o);
    if ((threadIdx.x & 31) == 0 && acc) atomicOr(&s, acc);
    __syncthreads();
    if (threadIdx.x == 0) g_is64 = (s == 0u) ? 1 : 0;
}

__global__ void zero_cnt_kernel(int M) {
    int n = blockIdx.x * blockDim.x + threadIdx.x;
    if (n >= M) return;
    g_cnt_c[n] = 0;
    g_cnt_r[n] = 0;
}

// ---------------------------------------------------------------- degrees + isr
__global__ void count_deg_kernel(const void* __restrict__ ei, int E) {
    int e0 = (blockIdx.x * blockDim.x + threadIdx.x) * 4;
    if (e0 >= E) return;
    if ((E & 3) == 0) {
        int c[4], r[4];
        edge_quad(ei, E, e0, c, r);
        #pragma unroll
        for (int j = 0; j < 4; ++j) {
            atomicAdd(&g_cnt_c[c[j]], 1);
            atomicAdd(&g_cnt_r[r[j]], 1);
        }
    } else {
        int m = min(4, E - e0);
        for (int j = 0; j < m; ++j) {
            atomicAdd(&g_cnt_c[edge_val(ei, e0 + j)], 1);
            atomicAdd(&g_cnt_r[edge_val(ei, (size_t)E + e0 + j)], 1);
        }
    }
}

__global__ void isr_kernel(int M) {
    int n = blockIdx.x * blockDim.x + threadIdx.x;
    if (n >= M) return;
    g_isr_in[n]  = rsqrtf((float)(g_cnt_c[n] + 1));
    g_isr_out[n] = rsqrtf((float)(g_cnt_r[n] + 1));
}

// ---------------------------------------------------------------- scan (2-level, per side)
__global__ void scan_block_sums(int sel, int M) {
    const int* cnt = sel ? g_cnt_r : g_cnt_c;
    int* bsum = sel ? g_bsum_r : g_bsum_c;
    __shared__ int s[SB];
    int t = threadIdx.x;
    int i = blockIdx.x * SB + t;
    s[t] = (i < M) ? cnt[i] : 0;
    __syncthreads();
    for (int d = SB >> 1; d > 0; d >>= 1) {
        if (t < d) s[t] += s[t + d];
        __syncthreads();
    }
    if (t == 0) bsum[blockIdx.x] = s[0];
}

__global__ void scan_bsum(int sel, int nb) {
    int* bsum = sel ? g_bsum_r : g_bsum_c;
    __shared__ int s[SB];
    int t = threadIdx.x;
    int v = (t < nb) ? bsum[t] : 0;
    s[t] = v;
    __syncthreads();
    for (int d = 1; d < SB; d <<= 1) {
        int tmp = (t >= d) ? s[t - d] : 0;
        __syncthreads();
        s[t] += tmp;
        __syncthreads();
    }
    if (t < nb) bsum[t] = s[t] - v;
}

__global__ void scan_final(int sel, int M) {
    const int* cnt = sel ? g_cnt_r : g_cnt_c;
    const int* bsum = sel ? g_bsum_r : g_bsum_c;
    int* off = sel ? g_off_r : g_off_c;
    int* cur = sel ? g_cur_r : g_cur_c;
    __shared__ int s[SB];
    int t = threadIdx.x;
    int i = blockIdx.x * SB + t;
    int v = (i < M) ? cnt[i] : 0;
    s[t] = v;
    __syncthreads();
    for (int d = 1; d < SB; d <<= 1) {
        int tmp = (t >= d) ? s[t - d] : 0;
        __syncthreads();
        s[t] += tmp;
        __syncthreads();
    }
    if (i < M) {
        int ex = s[t] - v + bsum[blockIdx.x];
        off[i] = ex;
        cur[i] = ex;
    }
}

// ---------------------------------------------------------------- fill (per side, 4 edges/thread)
__global__ void fill_c_kernel(const void* __restrict__ ei, int E) {
    int e0 = (blockIdx.x * blockDim.x + threadIdx.x) * 4;
    if (e0 >= E) return;
    if ((E & 3) == 0) {
        int c[4], r[4];
        edge_quad(ei, E, e0, c, r);
        #pragma unroll
        for (int j = 0; j < 4; ++j) {
            int pc = atomicAdd(&g_cur_c[c[j]], 1);
            g_efi[pc] = r[j];
        }
    } else {
        int m = min(4, E - e0);
        for (int j = 0; j < m; ++j) {
            int c = edge_val(ei, e0 + j);
            int r = edge_val(ei, (size_t)E + e0 + j);
            int pc = atomicAdd(&g_cur_c[c], 1);
            g_efi[pc] = r;
        }
    }
}

__global__ void fill_r_kernel(const void* __restrict__ ei, int E) {
    int e0 = (blockIdx.x * blockDim.x + threadIdx.x) * 4;
    if (e0 >= E) return;
    if ((E & 3) == 0) {
        int c[4], r[4];
        edge_quad(ei, E, e0, c, r);
        #pragma unroll
        for (int j = 0; j < 4; ++j) {
            int pr = atomicAdd(&g_cur_r[r[j]], 1);
            g_ebi[pr] = c[j];
        }
    } else {
        int m = min(4, E - e0);
        for (int j = 0; j < m; ++j) {
            int c = edge_val(ei, e0 + j);
            int r = edge_val(ei, (size_t)E + e0 + j);
            int pr = atomicAdd(&g_cur_r[r], 1);
            g_ebi[pr] = c;
        }
    }
}

// ---------------------------------------------------------------- W / x prep (fp16)
__global__ void w_conv_kernel(const float* __restrict__ Wf,
                              const float* __restrict__ Wb) {
    int idx = blockIdx.x * blockDim.x + threadIdx.x;
    if (idx >= 256 * 256) return;
    int n = idx >> 8, k = idx & 255;
    float v = (n < DH) ? Wf[n * DIN + k] : Wb[(n - DH) * DIN + k];
    g_wc[n * DIN + k] = __float2half_rn(v);
}

__global__ void x_conv_kernel(const float* __restrict__ x, int M) {
    int gid = blockIdx.x * blockDim.x + threadIdx.x;
    if (gid >= M * 64) return;
    int node = gid >> 6, q = gid & 63;
    float4 f = *(const float4*)(x + (size_t)node * DIN + q * 4);
    __half2 h0 = __floats2half2_rn(f.x, f.y);
    __half2 h1 = __floats2half2_rn(f.z, f.w);
    uint2 u = make_uint2(*(unsigned*)&h0, *(unsigned*)&h1);
    *(uint2*)(g_xa + (size_t)node * DIN + q * 4) = u;
}

// ---------------------------------------------------------------- HMMA GEMM
#define LDA 72
#define LDB 72
#define A_BUF (64 * LDA)
#define B_BUF (256 * LDB)
#define GEMM_SMEM ((2 * A_BUF + 2 * B_BUF) * 2)
#define NCHUNK 4

__device__ __forceinline__ void cp16(unsigned daddr, const void* src, unsigned sz) {
    asm volatile("cp.async.ca.shared.global [%0], [%1], 16, %2;"
                 :: "r"(daddr), "l"(src), "r"(sz) : "memory");
}

__global__ __launch_bounds__(256)
void gemm_hmma_kernel(int M)
{
    extern __shared__ __align__(16) __half smem[];
    __half* As = smem;
    __half* Bs = smem + 2 * A_BUF;

    const int t   = threadIdx.x;
    const int wid = t >> 5;
    const int lid = t & 31;
    const int m0  = blockIdx.x * 64;
    const int wm  = (wid & 1) * 32;
    const int wn  = (wid >> 1) * 64;

    float c[2][8][4];
    #pragma unroll
    for (int i = 0; i < 2; ++i)
        #pragma unroll
        for (int j = 0; j < 8; ++j)
            #pragma unroll
            for (int q = 0; q < 4; ++q) c[i][j][q] = 0.f;

    unsigned as_base = (unsigned)__cvta_generic_to_shared(As);
    unsigned bs_base = (unsigned)__cvta_generic_to_shared(Bs);

    auto issue_load = [&](int ch) {
        int buf = ch & 1;
        int k0 = ch * 64;
        #pragma unroll
        for (int i = 0; i < 2; ++i) {
            int idx = t + 256 * i;
            int row = idx >> 3, kq = idx & 7;
            const __half* src = g_xa + (size_t)(m0 + row) * DIN + k0 + kq * 8;
            unsigned dst = as_base + (buf * A_BUF + row * LDA + kq * 8) * 2;
            cp16(dst, src, (m0 + row) < M ? 16u : 0u);
        }
        #pragma unroll
        for (int i = 0; i < 8; ++i) {
            int idx = t + 256 * i;
            int row = idx >> 3, kq = idx & 7;
            const __half* src = g_wc + (size_t)row * DIN + k0 + kq * 8;
            unsigned dst = bs_base + (buf * B_BUF + row * LDB + kq * 8) * 2;
            cp16(dst, src, 16u);
        }
        asm volatile("cp.async.commit_group;" ::: "memory");
    };

    issue_load(0);
    issue_load(1);

    #pragma unroll 1
    for (int ch = 0; ch < NCHUNK; ++ch) {
        if (ch == NCHUNK - 1) asm volatile("cp.async.wait_group 0;" ::: "memory");
        else                  asm volatile("cp.async.wait_group 1;" ::: "memory");
        __syncthreads();

        const __half* A_ = As + (ch & 1) * A_BUF;
        const __half* B_ = Bs + (ch & 1) * B_BUF;

        #pragma unroll
        for (int k16 = 0; k16 < 4; ++k16) {
            int k0 = k16 * 16 + (lid & 3) * 2;
            unsigned a[2][4];
            #pragma unroll
            for (int mt = 0; mt < 2; ++mt) {
                int r = wm + mt * 16 + (lid >> 2);
                a[mt][0] = *(const unsigned*)(A_ + r * LDA + k0);
                a[mt][1] = *(const unsigned*)(A_ + (r + 8) * LDA + k0);
                a[mt][2] = *(const unsigned*)(A_ + r * LDA + k0 + 8);
                a[mt][3] = *(const unsigned*)(A_ + (r + 8) * LDA + k0 + 8);
            }
            #pragma unroll
            for (int nt = 0; nt < 8; ++nt) {
                int nrow = wn + nt * 8 + (lid >> 2);
                unsigned b0 = *(const unsigned*)(B_ + nrow * LDB + k0);
                unsigned b1 = *(const unsigned*)(B_ + nrow * LDB + k0 + 8);
                #pragma unroll
                for (int mt = 0; mt < 2; ++mt) {
                    asm volatile(
                        "mma.sync.aligned.m16n8k16.row.col.f32.f16.f16.f32 "
                        "{%0,%1,%2,%3}, {%4,%5,%6,%7}, {%8,%9}, {%0,%1,%2,%3};"
                        : "+f"(c[mt][nt][0]), "+f"(c[mt][nt][1]),
                          "+f"(c[mt][nt][2]), "+f"(c[mt][nt][3])
                        : "r"(a[mt][0]), "r"(a[mt][1]), "r"(a[mt][2]), "r"(a[mt][3]),
                          "r"(b0), "r"(b1));
                }
            }
        }
        __syncthreads();
        if (ch + 2 < NCHUNK) issue_load(ch + 2);
    }

    const float* scale_arr = (wn < DH) ? g_isr_out : g_isr_in;
    #pragma unroll
    for (int mt = 0; mt < 2; ++mt) {
        #pragma unroll
        for (int half2s = 0; half2s < 2; ++half2s) {
            int node = m0 + wm + mt * 16 + (lid >> 2) + half2s * 8;
            if (node >= M) continue;
            float sc = scale_arr[node];
            #pragma unroll
            for (int nt = 0; nt < 8; ++nt) {
                int n = wn + nt * 8 + (lid & 3) * 2;
                __half2 h = __floats2half2_rn(sc * c[mt][nt][half2s * 2],
                                              sc * c[mt][nt][half2s * 2 + 1]);
                __half* dst = (n < DH) ? (g_xf + (size_t)node * DH + n)
                                       : (g_xb + (size_t)node * DH + (n - DH));
                *(__half2*)dst = h;
            }
        }
    }
}

// ---------------------------------------------------------------- gather (CSR, MLP=8)
__global__ __launch_bounds__(256)
void gather_kernel(int sel, const float* __restrict__ bias,
                   float* __restrict__ y, int M)
{
    int lane = threadIdx.x & 31;
    int n = (blockIdx.x * blockDim.x + threadIdx.x) >> 5;
    if (n >= M) return;

    const int* elist   = sel ? g_ebi : g_efi;
    const int* off     = sel ? g_off_r : g_off_c;
    const int* cnt     = sel ? g_cnt_r : g_cnt_c;
    const __half* feat = sel ? g_xb : g_xf;
    float nscale = sel ? g_isr_out[n] : g_isr_in[n];
    int ycol0 = sel ? 32 : 0;

    int beg = off[n];
    int deg = cnt[n];

    float4 acc;
    {
        uint2 rv = *(const uint2*)(feat + (size_t)n * DH + lane * 4);
        float2 f0 = __half22float2(*(__half2*)&rv.x);
        float2 f1 = __half22float2(*(__half2*)&rv.y);
        acc = make_float4(f0.x, f0.y, f1.x, f1.y);
    }

    for (int base = 0; base < deg; base += 32) {
        int e = base + lane;
        int src = (e < deg) ? __ldg(elist + beg + e) : 0;
        int m = min(32, deg - base);
        int j = 0;
        for (; j + 8 <= m; j += 8) {
            uint2 v[8];
            #pragma unroll
            for (int u = 0; u < 8; ++u) {
                int s = __shfl_sync(0xffffffffu, src, j + u);
                v[u] = __ldg((const uint2*)(feat + (size_t)s * DH) + lane);
            }
            #pragma unroll
            for (int u = 0; u < 8; ++u) {
                float2 a0 = __half22float2(*(__half2*)&v[u].x);
                float2 a1 = __half22float2(*(__half2*)&v[u].y);
                acc.x += a0.x; acc.y += a0.y; acc.z += a1.x; acc.w += a1.y;
            }
        }
        for (; j < m; ++j) {
            int s0 = __shfl_sync(0xffffffffu, src, j);
            uint2 v0 = __ldg((const uint2*)(feat + (size_t)s0 * DH) + lane);
            float2 a0 = __half22float2(*(__half2*)&v0.x);
            float2 a1 = __half22float2(*(__half2*)&v0.y);
            acc.x += a0.x; acc.y += a0.y; acc.z += a1.x; acc.w += a1.y;
        }
    }

    float4 b = ((const float4*)(bias + sel * DH))[lane];
    float4 o = make_float4(b.x + nscale * acc.x, b.y + nscale * acc.y,
                           b.z + nscale * acc.z, b.w + nscale * acc.w);
    ((float4*)y)[(size_t)n * 64 + ycol0 + lane] = o;
}

// ---------------------------------------------------------------- launch
extern "C" void kernel_launch(void* const* d_in, const int* in_sizes, int n_in,
                              void* d_out, int out_size)
{
    const float* x    = (const float*)d_in[0];
    const void*  ei   = d_in[1];
    const float* Wf   = (const float*)d_in[2];
    const float* Wb   = (const float*)d_in[3];
    const float* bias = (const float*)d_in[4];
    float*       y    = (float*)d_out;

    int M  = in_sizes[0] / DIN;
    int E2 = in_sizes[1];
    int E  = E2 / 2;
    int nb = (M + SB - 1) / SB;

    static cudaStream_t s1 = nullptr, s2 = nullptr, s3 = nullptr;
    static cudaEvent_t ev_fork = nullptr, ev_zero = nullptr, ev_cnt = nullptr,
                       ev_isr = nullptr, ev_fc = nullptr, ev_gemm = nullptr,
                       ev_b = nullptr;
    static bool tried = false;
    if (!tried) {
        tried = true;
        cudaFuncSetAttribute(gemm_hmma_kernel,
                             cudaFuncAttributeMaxDynamicSharedMemorySize, GEMM_SMEM);
        bool ok = (cudaStreamCreateWithFlags(&s1, cudaStreamNonBlocking) == cudaSuccess)
               && (cudaStreamCreateWithFlags(&s2, cudaStreamNonBlocking) == cudaSuccess)
               && (cudaStreamCreateWithFlags(&s3, cudaStreamNonBlocking) == cudaSuccess);
        if (ok) {
            cudaEventCreateWithFlags(&ev_fork, cudaEventDisableTiming);
            cudaEventCreateWithFlags(&ev_zero, cudaEventDisableTiming);
            cudaEventCreateWithFlags(&ev_cnt, cudaEventDisableTiming);
            cudaEventCreateWithFlags(&ev_isr, cudaEventDisableTiming);
            cudaEventCreateWithFlags(&ev_fc, cudaEventDisableTiming);
            cudaEventCreateWithFlags(&ev_gemm, cudaEventDisableTiming);
            cudaEventCreateWithFlags(&ev_b, cudaEventDisableTiming);
        } else { s1 = s2 = s3 = nullptr; }
    }

    int eblocks4 = (E + 4 * 256 - 1) / (4 * 256);
    int gblocks = (M * 32 + 255) / 256;

    if (s1) {
        cudaEventRecord(ev_fork, 0);
        cudaStreamWaitEvent(s1, ev_fork, 0);
        cudaStreamWaitEvent(s2, ev_fork, 0);
        cudaStreamWaitEvent(s3, ev_fork, 0);

        // s2: zero counts (concurrent with detect)
        zero_cnt_kernel<<<(M + 255) / 256, 256, 0, s2>>>(M);
        cudaEventRecord(ev_zero, s2);

        // s1: detect -> count -> c-side scan chain -> fill_c
        detect_flag_kernel<<<1, 1024, 0, s1>>>((const unsigned*)ei, E2);
        cudaStreamWaitEvent(s1, ev_zero, 0);
        count_deg_kernel<<<eblocks4, 256, 0, s1>>>(ei, E);
        cudaEventRecord(ev_cnt, s1);
        scan_block_sums<<<nb, SB, 0, s1>>>(0, M);
        scan_bsum<<<1, SB, 0, s1>>>(0, nb);
        scan_final<<<nb, SB, 0, s1>>>(0, M);
        fill_c_kernel<<<eblocks4, 256, 0, s1>>>(ei, E);
        cudaEventRecord(ev_fc, s1);

        // s3: isr right after counts (off the scan critical path)
        cudaStreamWaitEvent(s3, ev_cnt, 0);
        isr_kernel<<<(M + 255) / 256, 256, 0, s3>>>(M);
        cudaEventRecord(ev_isr, s3);

        // s2: r-side scan chain -> fill_r
        cudaStreamWaitEvent(s2, ev_cnt, 0);
        scan_block_sums<<<nb, SB, 0, s2>>>(1, M);
        scan_bsum<<<1, SB, 0, s2>>>(1, nb);
        scan_final<<<nb, SB, 0, s2>>>(1, M);
        fill_r_kernel<<<eblocks4, 256, 0, s2>>>(ei, E);

        // main: GEMM path
        w_conv_kernel<<<256, 256>>>(Wf, Wb);
        x_conv_kernel<<<(M * 64 + 255) / 256, 256>>>(x, M);
        cudaStreamWaitEvent(0, ev_isr, 0);
        gemm_hmma_kernel<<<(M + 63) / 64, 256, GEMM_SMEM>>>(M);
        cudaEventRecord(ev_gemm, 0);

        // gathers
        cudaStreamWaitEvent(0, ev_fc, 0);
        gather_kernel<<<gblocks, 256, 0, 0>>>(0, bias, y, M);
        cudaStreamWaitEvent(s2, ev_gemm, 0);
        gather_kernel<<<gblocks, 256, 0, s2>>>(1, bias, y, M);
        cudaEventRecord(ev_b, s2);
        cudaStreamWaitEvent(0, ev_b, 0);
    } else {
        // serial fallback
        zero_cnt_kernel<<<(M + 255) / 256, 256>>>(M);
        detect_flag_kernel<<<1, 1024>>>((const unsigned*)ei, E2);
        count_deg_kernel<<<eblocks4, 256>>>(ei, E);
        isr_kernel<<<(M + 255) / 256, 256>>>(M);
        scan_block_sums<<<nb, SB>>>(0, M);
        scan_bsum<<<1, SB>>>(0, nb);
        scan_final<<<nb, SB>>>(0, M);
        fill_c_kernel<<<eblocks4, 256>>>(ei, E);
        scan_block_sums<<<nb, SB>>>(1, M);
        scan_bsum<<<1, SB>>>(1, nb);
        scan_final<<<nb, SB>>>(1, M);
        fill_r_kernel<<<eblocks4, 256>>>(ei, E);
        w_conv_kernel<<<256, 256>>>(Wf, Wb);
        x_conv_kernel<<<(M * 64 + 255) / 256, 256>>>(x, M);
        gemm_hmma_kernel<<<(M + 63) / 64, 256, GEMM_SMEM>>>(M);
        gather_kernel<<<gblocks, 256>>>(0, bias, y, M);
        gather_kernel<<<gblocks, 256>>>(1, bias, y, M);
    }
}

// round 10
// speedup vs baseline: 1.0434x; 1.0434x over previous
#include <cuda_runtime.h>
#include <cuda_fp16.h>
#include <cstdint>
#include <cstddef>

#define NN_MAX 100000
#define NE_MAX 1600000
#define DIN 256
#define DH 128
#define SB 512

typedef unsigned long long ull;

// ---------------------------------------------------------------- scratch
__device__ __half g_xf[NN_MAX * DH];   // isr_out[n] * (x @ W_f^T)[n]  (fp16)
__device__ __half g_xb[NN_MAX * DH];   // isr_in[n]  * (x @ W_b^T)[n]  (fp16)
__device__ __half g_xa[NN_MAX * DIN];  // x as fp16
__device__ __half g_wc[256 * DIN];     // W fp16 [n][k] (Wf rows 0-127, Wb 128-255)
__device__ int   g_cnt_c[NN_MAX];
__device__ int   g_cnt_r[NN_MAX];
__device__ float g_isr_in[NN_MAX];
__device__ float g_isr_out[NN_MAX];
__device__ int   g_off_c[NN_MAX];
__device__ int   g_off_r[NN_MAX];
__device__ int   g_bsum_c[SB];
__device__ int   g_bsum_r[SB];
__device__ int   g_rank_c[NE_MAX];     // rank of edge within its col bucket
__device__ int   g_rank_r[NE_MAX];     // rank of edge within its row bucket
__device__ int   g_efi[NE_MAX];        // edges sorted by col: src=row
__device__ int   g_ebi[NE_MAX];        // edges sorted by row: src=col
__device__ int   g_is64;

__device__ __forceinline__ int edge_val(const void* ei, size_t idx) {
    if (g_is64) return (int)((const long long*)ei)[idx];
    return ((const int*)ei)[idx];
}

// ---------------------------------------------------------------- dtype detect
__global__ void detect_flag_kernel(const unsigned* __restrict__ w, int nwords) {
    __shared__ unsigned s;
    if (threadIdx.x == 0) s = 0;
    __syncthreads();
    unsigned acc = 0;
    for (int i = threadIdx.x; i < 16384 && 2 * i + 1 < nwords; i += blockDim.x)
        acc |= w[2 * i + 1];
    #pragma unroll
    for (int o = 16; o > 0; o >>= 1)
        acc |= __shfl_xor_sync(0xffffffffu, acc, o);
    if ((threadIdx.x & 31) == 0 && acc) atomicOr(&s, acc);
    __syncthreads();
    if (threadIdx.x == 0) g_is64 = (s == 0u) ? 1 : 0;
}

// ---------------------------------------------------------------- count (+rank record)
__global__ void count_deg_kernel(const void* __restrict__ ei, int E) {
    int e = blockIdx.x * blockDim.x + threadIdx.x;
    if (e >= E) return;
    int c = edge_val(ei, e);
    int r = edge_val(ei, (size_t)E + e);
    g_rank_c[e] = atomicAdd(&g_cnt_c[c], 1);
    g_rank_r[e] = atomicAdd(&g_cnt_r[r], 1);
}

__global__ void isr_kernel(int M) {
    int n = blockIdx.x * blockDim.x + threadIdx.x;
    if (n >= M) return;
    g_isr_in[n]  = rsqrtf((float)(g_cnt_c[n] + 1));
    g_isr_out[n] = rsqrtf((float)(g_cnt_r[n] + 1));
}

// ---------------------------------------------------------------- scan (2-level, per side)
__global__ void scan_block_sums(int sel, int M) {
    const int* cnt = sel ? g_cnt_r : g_cnt_c;
    int* bsum = sel ? g_bsum_r : g_bsum_c;
    __shared__ int s[SB];
    int t = threadIdx.x;
    int i = blockIdx.x * SB + t;
    s[t] = (i < M) ? cnt[i] : 0;
    __syncthreads();
    for (int d = SB >> 1; d > 0; d >>= 1) {
        if (t < d) s[t] += s[t + d];
        __syncthreads();
    }
    if (t == 0) bsum[blockIdx.x] = s[0];
}

__global__ void scan_bsum(int sel, int nb) {
    int* bsum = sel ? g_bsum_r : g_bsum_c;
    __shared__ int s[SB];
    int t = threadIdx.x;
    int v = (t < nb) ? bsum[t] : 0;
    s[t] = v;
    __syncthreads();
    for (int d = 1; d < SB; d <<= 1) {
        int tmp = (t >= d) ? s[t - d] : 0;
        __syncthreads();
        s[t] += tmp;
        __syncthreads();
    }
    if (t < nb) bsum[t] = s[t] - v;
}

__global__ void scan_final(int sel, int M) {
    const int* cnt = sel ? g_cnt_r : g_cnt_c;
    const int* bsum = sel ? g_bsum_r : g_bsum_c;
    int* off = sel ? g_off_r : g_off_c;
    __shared__ int s[SB];
    int t = threadIdx.x;
    int i = blockIdx.x * SB + t;
    int v = (i < M) ? cnt[i] : 0;
    s[t] = v;
    __syncthreads();
    for (int d = 1; d < SB; d <<= 1) {
        int tmp = (t >= d) ? s[t - d] : 0;
        __syncthreads();
        s[t] += tmp;
        __syncthreads();
    }
    if (i < M)
        off[i] = s[t] - v + bsum[blockIdx.x];
}

// ---------------------------------------------------------------- fill (atomic-free scatter)
__global__ void fill_c_kernel(const void* __restrict__ ei, int E) {
    int e = blockIdx.x * blockDim.x + threadIdx.x;
    if (e >= E) return;
    int c = edge_val(ei, e);
    int r = edge_val(ei, (size_t)E + e);
    g_efi[g_off_c[c] + g_rank_c[e]] = r;
}

__global__ void fill_r_kernel(const void* __restrict__ ei, int E) {
    int e = blockIdx.x * blockDim.x + threadIdx.x;
    if (e >= E) return;
    int c = edge_val(ei, e);
    int r = edge_val(ei, (size_t)E + e);
    g_ebi[g_off_r[r] + g_rank_r[e]] = c;
}

// ---------------------------------------------------------------- W / x prep (fp16)
__global__ void w_conv_kernel(const float* __restrict__ Wf,
                              const float* __restrict__ Wb) {
    int idx = blockIdx.x * blockDim.x + threadIdx.x;
    if (idx >= 256 * 256) return;
    int n = idx >> 8, k = idx & 255;
    float v = (n < DH) ? Wf[n * DIN + k] : Wb[(n - DH) * DIN + k];
    g_wc[n * DIN + k] = __float2half_rn(v);
}

__global__ void x_conv_kernel(const float* __restrict__ x, int M) {
    int gid = blockIdx.x * blockDim.x + threadIdx.x;
    if (gid >= M * 64) return;
    int node = gid >> 6, q = gid & 63;
    float4 f = *(const float4*)(x + (size_t)node * DIN + q * 4);
    __half2 h0 = __floats2half2_rn(f.x, f.y);
    __half2 h1 = __floats2half2_rn(f.z, f.w);
    uint2 u = make_uint2(*(unsigned*)&h0, *(unsigned*)&h1);
    *(uint2*)(g_xa + (size_t)node * DIN + q * 4) = u;
}

// ---------------------------------------------------------------- HMMA GEMM
#define LDA 72
#define LDB 72
#define A_BUF (64 * LDA)
#define B_BUF (256 * LDB)
#define GEMM_SMEM ((2 * A_BUF + 2 * B_BUF) * 2)
#define NCHUNK 4

__device__ __forceinline__ void cp16(unsigned daddr, const void* src, unsigned sz) {
    asm volatile("cp.async.ca.shared.global [%0], [%1], 16, %2;"
                 :: "r"(daddr), "l"(src), "r"(sz) : "memory");
}

__global__ __launch_bounds__(256)
void gemm_hmma_kernel(int M)
{
    extern __shared__ __align__(16) __half smem[];
    __half* As = smem;
    __half* Bs = smem + 2 * A_BUF;

    const int t   = threadIdx.x;
    const int wid = t >> 5;
    const int lid = t & 31;
    const int m0  = blockIdx.x * 64;
    const int wm  = (wid & 1) * 32;
    const int wn  = (wid >> 1) * 64;

    float c[2][8][4];
    #pragma unroll
    for (int i = 0; i < 2; ++i)
        #pragma unroll
        for (int j = 0; j < 8; ++j)
            #pragma unroll
            for (int q = 0; q < 4; ++q) c[i][j][q] = 0.f;

    unsigned as_base = (unsigned)__cvta_generic_to_shared(As);
    unsigned bs_base = (unsigned)__cvta_generic_to_shared(Bs);

    auto issue_load = [&](int ch) {
        int buf = ch & 1;
        int k0 = ch * 64;
        #pragma unroll
        for (int i = 0; i < 2; ++i) {
            int idx = t + 256 * i;
            int row = idx >> 3, kq = idx & 7;
            const __half* src = g_xa + (size_t)(m0 + row) * DIN + k0 + kq * 8;
            unsigned dst = as_base + (buf * A_BUF + row * LDA + kq * 8) * 2;
            cp16(dst, src, (m0 + row) < M ? 16u : 0u);
        }
        #pragma unroll
        for (int i = 0; i < 8; ++i) {
            int idx = t + 256 * i;
            int row = idx >> 3, kq = idx & 7;
            const __half* src = g_wc + (size_t)row * DIN + k0 + kq * 8;
            unsigned dst = bs_base + (buf * B_BUF + row * LDB + kq * 8) * 2;
            cp16(dst, src, 16u);
        }
        asm volatile("cp.async.commit_group;" ::: "memory");
    };

    issue_load(0);
    issue_load(1);

    #pragma unroll 1
    for (int ch = 0; ch < NCHUNK; ++ch) {
        if (ch == NCHUNK - 1) asm volatile("cp.async.wait_group 0;" ::: "memory");
        else                  asm volatile("cp.async.wait_group 1;" ::: "memory");
        __syncthreads();

        const __half* A_ = As + (ch & 1) * A_BUF;
        const __half* B_ = Bs + (ch & 1) * B_BUF;

        #pragma unroll
        for (int k16 = 0; k16 < 4; ++k16) {
            int k0 = k16 * 16 + (lid & 3) * 2;
            unsigned a[2][4];
            #pragma unroll
            for (int mt = 0; mt < 2; ++mt) {
                int r = wm + mt * 16 + (lid >> 2);
                a[mt][0] = *(const unsigned*)(A_ + r * LDA + k0);
                a[mt][1] = *(const unsigned*)(A_ + (r + 8) * LDA + k0);
                a[mt][2] = *(const unsigned*)(A_ + r * LDA + k0 + 8);
                a[mt][3] = *(const unsigned*)(A_ + (r + 8) * LDA + k0 + 8);
            }
            #pragma unroll
            for (int nt = 0; nt < 8; ++nt) {
                int nrow = wn + nt * 8 + (lid >> 2);
                unsigned b0 = *(const unsigned*)(B_ + nrow * LDB + k0);
                unsigned b1 = *(const unsigned*)(B_ + nrow * LDB + k0 + 8);
                #pragma unroll
                for (int mt = 0; mt < 2; ++mt) {
                    asm volatile(
                        "mma.sync.aligned.m16n8k16.row.col.f32.f16.f16.f32 "
                        "{%0,%1,%2,%3}, {%4,%5,%6,%7}, {%8,%9}, {%0,%1,%2,%3};"
                        : "+f"(c[mt][nt][0]), "+f"(c[mt][nt][1]),
                          "+f"(c[mt][nt][2]), "+f"(c[mt][nt][3])
                        : "r"(a[mt][0]), "r"(a[mt][1]), "r"(a[mt][2]), "r"(a[mt][3]),
                          "r"(b0), "r"(b1));
                }
            }
        }
        __syncthreads();
        if (ch + 2 < NCHUNK) issue_load(ch + 2);
    }

    const float* scale_arr = (wn < DH) ? g_isr_out : g_isr_in;
    #pragma unroll
    for (int mt = 0; mt < 2; ++mt) {
        #pragma unroll
        for (int half2s = 0; half2s < 2; ++half2s) {
            int node = m0 + wm + mt * 16 + (lid >> 2) + half2s * 8;
            if (node >= M) continue;
            float sc = scale_arr[node];
            #pragma unroll
            for (int nt = 0; nt < 8; ++nt) {
                int n = wn + nt * 8 + (lid & 3) * 2;
                __half2 h = __floats2half2_rn(sc * c[mt][nt][half2s * 2],
                                              sc * c[mt][nt][half2s * 2 + 1]);
                __half* dst = (n < DH) ? (g_xf + (size_t)node * DH + n)
                                       : (g_xb + (size_t)node * DH + (n - DH));
                *(__half2*)dst = h;
            }
        }
    }
}

// ---------------------------------------------------------------- gather (CSR, MLP=4)
__global__ __launch_bounds__(256)
void gather_kernel(int sel, const float* __restrict__ bias,
                   float* __restrict__ y, int M)
{
    int lane = threadIdx.x & 31;
    int n = (blockIdx.x * blockDim.x + threadIdx.x) >> 5;
    if (n >= M) return;

    const int* elist   = sel ? g_ebi : g_efi;
    const int* off     = sel ? g_off_r : g_off_c;
    const int* cnt     = sel ? g_cnt_r : g_cnt_c;
    const __half* feat = sel ? g_xb : g_xf;
    float nscale = sel ? g_isr_out[n] : g_isr_in[n];
    int ycol0 = sel ? 32 : 0;

    int beg = off[n];
    int deg = cnt[n];

    float4 acc;
    {
        uint2 rv = *(const uint2*)(feat + (size_t)n * DH + lane * 4);
        float2 f0 = __half22float2(*(__half2*)&rv.x);
        float2 f1 = __half22float2(*(__half2*)&rv.y);
        acc = make_float4(f0.x, f0.y, f1.x, f1.y);
    }

    for (int base = 0; base < deg; base += 32) {
        int e = base + lane;
        int src = (e < deg) ? __ldg(elist + beg + e) : 0;
        int m = min(32, deg - base);
        int j = 0;
        for (; j + 4 <= m; j += 4) {
            int s0 = __shfl_sync(0xffffffffu, src, j);
            int s1 = __shfl_sync(0xffffffffu, src, j + 1);
            int s2 = __shfl_sync(0xffffffffu, src, j + 2);
            int s3 = __shfl_sync(0xffffffffu, src, j + 3);
            uint2 v0 = __ldg((const uint2*)(feat + (size_t)s0 * DH) + lane);
            uint2 v1 = __ldg((const uint2*)(feat + (size_t)s1 * DH) + lane);
            uint2 v2 = __ldg((const uint2*)(feat + (size_t)s2 * DH) + lane);
            uint2 v3 = __ldg((const uint2*)(feat + (size_t)s3 * DH) + lane);
            float2 a0 = __half22float2(*(__half2*)&v0.x);
            float2 a1 = __half22float2(*(__half2*)&v0.y);
            acc.x += a0.x; acc.y += a0.y; acc.z += a1.x; acc.w += a1.y;
            a0 = __half22float2(*(__half2*)&v1.x);
            a1 = __half22float2(*(__half2*)&v1.y);
            acc.x += a0.x; acc.y += a0.y; acc.z += a1.x; acc.w += a1.y;
            a0 = __half22float2(*(__half2*)&v2.x);
            a1 = __half22float2(*(__half2*)&v2.y);
            acc.x += a0.x; acc.y += a0.y; acc.z += a1.x; acc.w += a1.y;
            a0 = __half22float2(*(__half2*)&v3.x);
            a1 = __half22float2(*(__half2*)&v3.y);
            acc.x += a0.x; acc.y += a0.y; acc.z += a1.x; acc.w += a1.y;
        }
        for (; j < m; ++j) {
            int s0 = __shfl_sync(0xffffffffu, src, j);
            uint2 v0 = __ldg((const uint2*)(feat + (size_t)s0 * DH) + lane);
            float2 a0 = __half22float2(*(__half2*)&v0.x);
            float2 a1 = __half22float2(*(__half2*)&v0.y);
            acc.x += a0.x; acc.y += a0.y; acc.z += a1.x; acc.w += a1.y;
        }
    }

    float4 b = ((const float4*)(bias + sel * DH))[lane];
    float4 o = make_float4(b.x + nscale * acc.x, b.y + nscale * acc.y,
                           b.z + nscale * acc.z, b.w + nscale * acc.w);
    ((float4*)y)[(size_t)n * 64 + ycol0 + lane] = o;
}

// ---------------------------------------------------------------- launch
extern "C" void kernel_launch(void* const* d_in, const int* in_sizes, int n_in,
                              void* d_out, int out_size)
{
    const float* x    = (const float*)d_in[0];
    const void*  ei   = d_in[1];
    const float* Wf   = (const float*)d_in[2];
    const float* Wb   = (const float*)d_in[3];
    const float* bias = (const float*)d_in[4];
    float*       y    = (float*)d_out;

    int M  = in_sizes[0] / DIN;
    int E2 = in_sizes[1];
    int E  = E2 / 2;
    int nb = (M + SB - 1) / SB;

    static cudaStream_t s1 = nullptr, s2 = nullptr, s3 = nullptr;
    static cudaEvent_t ev_fork = nullptr, ev_zero = nullptr, ev_cnt = nullptr,
                       ev_isr = nullptr, ev_fc = nullptr, ev_gemm = nullptr,
                       ev_b = nullptr;
    static void *p_cnt_c = nullptr, *p_cnt_r = nullptr;
    static bool tried = false;
    if (!tried) {
        tried = true;
        cudaFuncSetAttribute(gemm_hmma_kernel,
                             cudaFuncAttributeMaxDynamicSharedMemorySize, GEMM_SMEM);
        cudaGetSymbolAddress(&p_cnt_c, g_cnt_c);
        cudaGetSymbolAddress(&p_cnt_r, g_cnt_r);
        bool ok = (cudaStreamCreateWithFlags(&s1, cudaStreamNonBlocking) == cudaSuccess)
               && (cudaStreamCreateWithFlags(&s2, cudaStreamNonBlocking) == cudaSuccess)
               && (cudaStreamCreateWithFlags(&s3, cudaStreamNonBlocking) == cudaSuccess);
        if (ok) {
            cudaEventCreateWithFlags(&ev_fork, cudaEventDisableTiming);
            cudaEventCreateWithFlags(&ev_zero, cudaEventDisableTiming);
            cudaEventCreateWithFlags(&ev_cnt, cudaEventDisableTiming);
            cudaEventCreateWithFlags(&ev_isr, cudaEventDisableTiming);
            cudaEventCreateWithFlags(&ev_fc, cudaEventDisableTiming);
            cudaEventCreateWithFlags(&ev_gemm, cudaEventDisableTiming);
            cudaEventCreateWithFlags(&ev_b, cudaEventDisableTiming);
        } else { s1 = s2 = s3 = nullptr; }
    }

    int eblocks = (E + 255) / 256;
    int gblocks = (M * 32 + 255) / 256;

    if (s1 && p_cnt_c && p_cnt_r) {
        cudaEventRecord(ev_fork, 0);
        cudaStreamWaitEvent(s1, ev_fork, 0);
        cudaStreamWaitEvent(s2, ev_fork, 0);
        cudaStreamWaitEvent(s3, ev_fork, 0);

        // s2: zero counts via memset (concurrent with detect)
        cudaMemsetAsync(p_cnt_c, 0, (size_t)M * sizeof(int), s2);
        cudaMemsetAsync(p_cnt_r, 0, (size_t)M * sizeof(int), s2);
        cudaEventRecord(ev_zero, s2);

        // s1: detect -> count(+ranks) -> c-side scans -> fill_c
        detect_flag_kernel<<<1, 1024, 0, s1>>>((const unsigned*)ei, E2);
        cudaStreamWaitEvent(s1, ev_zero, 0);
        count_deg_kernel<<<eblocks, 256, 0, s1>>>(ei, E);
        cudaEventRecord(ev_cnt, s1);
        scan_block_sums<<<nb, SB, 0, s1>>>(0, M);
        scan_bsum<<<1, SB, 0, s1>>>(0, nb);
        scan_final<<<nb, SB, 0, s1>>>(0, M);
        fill_c_kernel<<<eblocks, 256, 0, s1>>>(ei, E);
        cudaEventRecord(ev_fc, s1);

        // s3: isr right after counts (off the scan critical path)
        cudaStreamWaitEvent(s3, ev_cnt, 0);
        isr_kernel<<<(M + 255) / 256, 256, 0, s3>>>(M);
        cudaEventRecord(ev_isr, s3);

        // s2: r-side scans -> fill_r
        cudaStreamWaitEvent(s2, ev_cnt, 0);
        scan_block_sums<<<nb, SB, 0, s2>>>(1, M);
        scan_bsum<<<1, SB, 0, s2>>>(1, nb);
        scan_final<<<nb, SB, 0, s2>>>(1, M);
        fill_r_kernel<<<eblocks, 256, 0, s2>>>(ei, E);

        // main: GEMM path
        w_conv_kernel<<<256, 256>>>(Wf, Wb);
        x_conv_kernel<<<(M * 64 + 255) / 256, 256>>>(x, M);
        cudaStreamWaitEvent(0, ev_isr, 0);
        gemm_hmma_kernel<<<(M + 63) / 64, 256, GEMM_SMEM>>>(M);
        cudaEventRecord(ev_gemm, 0);

        // gathers
        cudaStreamWaitEvent(0, ev_fc, 0);
        gather_kernel<<<gblocks, 256, 0, 0>>>(0, bias, y, M);
        cudaStreamWaitEvent(s2, ev_gemm, 0);
        gather_kernel<<<gblocks, 256, 0, s2>>>(1, bias, y, M);
        cudaEventRecord(ev_b, s2);
        cudaStreamWaitEvent(0, ev_b, 0);
    } else {
        // serial fallback (kernel-based zero via memset on default stream)
        if (p_cnt_c && p_cnt_r) {
            cudaMemsetAsync(p_cnt_c, 0, (size_t)M * sizeof(int), 0);
            cudaMemsetAsync(p_cnt_r, 0, (size_t)M * sizeof(int), 0);
        }
        detect_flag_kernel<<<1, 1024>>>((const unsigned*)ei, E2);
        count_deg_kernel<<<eblocks, 256>>>(ei, E);
        isr_kernel<<<(M + 255) / 256, 256>>>(M);
        scan_block_sums<<<nb, SB>>>(0, M);
        scan_bsum<<<1, SB>>>(0, nb);
        scan_final<<<nb, SB>>>(0, M);
        fill_c_kernel<<<eblocks, 256>>>(ei, E);
        scan_block_sums<<<nb, SB>>>(1, M);
        scan_bsum<<<1, SB>>>(1, nb);
        scan_final<<<nb, SB>>>(1, M);
        fill_r_kernel<<<eblocks, 256>>>(ei, E);
        w_conv_kernel<<<256, 256>>>(Wf, Wb);
        x_conv_kernel<<<(M * 64 + 255) / 256, 256>>>(x, M);
        gemm_hmma_kernel<<<(M + 63) / 64, 256, GEMM_SMEM>>>(M);
        gather_kernel<<<gblocks, 256>>>(0, bias, y, M);
        gather_kernel<<<gblocks, 256>>>(1, bias, y, M);
    }
}